// round 13
// baseline (speedup 1.0000x reference)
#include <cuda_runtime.h>
#include <cuda_bf16.h>

#define N_IN    11008
#define N_OUT   4096
#define TOPK_K  5504
#define N_CACHE 64
#define NBW     344            // ceil(11008/32)
#define TPB     1024
#define GRID    128            // 128 blocks x 32 warps = 4096 warps = 1 row/warp

// ---- device-global scratch (allocation-free; fully rewritten each call) ----
__device__ unsigned g_maskbits[NBW];
__device__ int g_inter[N_CACHE];
__device__ unsigned g_arrive;     // launch arrival counter (monotonic)
__device__ unsigned g_mask_done;  // +1 per launch when maskbits published
__device__ unsigned g_int_done;   // +64 per launch when intersections written

// Sleep-poll until *addr >= target (acquire).
__device__ __forceinline__ void poll_ge(const unsigned* addr, unsigned target) {
    unsigned cur;
    for (;;) {
        asm volatile("ld.acquire.gpu.u32 %0, [%1];"
                     : "=r"(cur) : "l"(addr) : "memory");
        if (cur >= target) break;
        __nanosleep(64);
    }
}

// 1024-thread block inclusive scan (one int per thread).
__device__ __forceinline__ int scan1024(int v, int lane, int wid, int* sbuf) {
    __syncthreads();
    #pragma unroll
    for (int o = 1; o < 32; o <<= 1) {
        int t = __shfl_up_sync(0xffffffffu, v, o);
        if (lane >= o) v += t;
    }
    if (lane == 31) sbuf[wid] = v;
    __syncthreads();
    if (wid == 0) {
        int w = sbuf[lane];
        #pragma unroll
        for (int o = 1; o < 32; o <<= 1) {
            int t = __shfl_up_sync(0xffffffffu, w, o);
            if (lane >= o) w += t;
        }
        sbuf[lane] = w;
    }
    __syncthreads();
    if (wid > 0) v += sbuf[wid - 1];
    return v;
}

// ============================================================================
// Mega-kernel, ONE launch, 128 blocks x 1024 threads:
//   block 0:      smem radix select -> maskbits -> g_mask_done++
//   blocks 1..64: cbits (concurrent) -> poll mask -> intersection -> g_int_done++
//   ALL blocks:   poll int==64 -> local decision -> build xm in OWN smem
//                 -> GEMV (1 row/warp, proven 5.3 TB/s W pattern, x from smem)
// ============================================================================
__global__ void __launch_bounds__(TPB, 1)
mega_kernel(const float* __restrict__ x, const int* __restrict__ cached,
            const float* __restrict__ W, const float* __restrict__ bias,
            float* __restrict__ out) {
    __shared__ unsigned s_mem[N_IN];     // |x| bits / cbits, then float xm
    __shared__ unsigned hist[2048];
    __shared__ unsigned s_bits[NBW];
    __shared__ int scanbuf[32];
    __shared__ int s_b, s_G, s_need, s_use, s_best;
    __shared__ unsigned s_T, s_gen;

    const int b = blockIdx.x, tid = threadIdx.x;
    const int lane = tid & 31, wid = tid >> 5;

    if (tid == 0) s_gen = atomicAdd(&g_arrive, 1u) / GRID;   // launch generation
    __syncthreads();
    const unsigned gen = s_gen;

    if (b == 0) {
        // ---- fused stage + level-0 histogram (bits [30:21]) ----
        for (int i = tid; i < 2048; i += TPB) hist[i] = 0;
        for (int i = tid; i < NBW; i += TPB) s_bits[i] = 0;
        __syncthreads();
        for (int i = tid; i < N_IN; i += TPB) {
            unsigned u = __float_as_uint(x[i]) & 0x7FFFFFFFu;
            s_mem[i] = u;
            atomicAdd(&hist[u >> 21], 1u);
        }
        __syncthreads();
        {
            const int j0 = 2047 - 2 * tid, j1 = j0 - 1;
            const int h0 = hist[j0], h1 = hist[j1];
            int S = scan1024(h0 + h1, lane, wid, scanbuf);
            int excl = S - h0 - h1;
            const int Kr = TOPK_K;
            if (excl + h0 >= Kr && excl < Kr)   { s_b = j0; s_G = excl; }
            else if (S >= Kr && excl + h0 < Kr) { s_b = j1; s_G = excl + h0; }
        }
        __syncthreads();
        const int b0 = s_b, G0 = s_G;

        // ---- level 1: bits [20:10] ----
        __syncthreads();
        for (int i = tid; i < 2048; i += TPB) hist[i] = 0;
        __syncthreads();
        for (int i = tid; i < N_IN; i += TPB) {
            unsigned u = s_mem[i];
            if ((int)(u >> 21) == b0) atomicAdd(&hist[(u >> 10) & 0x7FF], 1u);
        }
        __syncthreads();
        {
            const int j0 = 2047 - 2 * tid, j1 = j0 - 1;
            const int h0 = hist[j0], h1 = hist[j1];
            int S = scan1024(h0 + h1, lane, wid, scanbuf);
            int excl = S - h0 - h1;
            const int Kr = TOPK_K - G0;
            if (excl + h0 >= Kr && excl < Kr)   { s_b = j0; s_G = G0 + excl; }
            else if (S >= Kr && excl + h0 < Kr) { s_b = j1; s_G = G0 + excl + h0; }
        }
        __syncthreads();
        const int b1 = s_b, G1 = s_G;

        // ---- level 2: bits [9:0] ----
        __syncthreads();
        for (int i = tid; i < 2048; i += TPB) hist[i] = 0;
        __syncthreads();
        const unsigned top22 = ((unsigned)b0 << 21) | ((unsigned)b1 << 10);
        for (int i = tid; i < N_IN; i += TPB) {
            unsigned u = s_mem[i];
            if ((u & 0xFFFFFC00u) == top22) atomicAdd(&hist[u & 0x3FF], 1u);
        }
        __syncthreads();
        {
            const int j = 1023 - tid;
            const int h = (int)hist[j];
            int S = scan1024(h, lane, wid, scanbuf);
            int excl = S - h;
            const int Kr = TOPK_K - G1;
            if (S >= Kr && excl < Kr) { s_T = top22 | (unsigned)j; s_need = Kr - excl; }
        }
        __syncthreads();
        const unsigned T = s_T;
        const int need = s_need;

        // ---- mask build with smallest-index tie-break ----
        const int CHUNK = (N_IN + TPB - 1) / TPB;   // 11
        const int start = tid * CHUNK;
        const int end   = min(start + CHUNK, N_IN);

        int tieCnt = 0;
        for (int i = start; i < end; i++)
            if (s_mem[i] == T) tieCnt++;
        int incl = scan1024(tieCnt, lane, wid, scanbuf);
        int rank = incl - tieCnt;

        for (int i = start; i < end; i++) {
            unsigned u = s_mem[i];
            bool sel;
            if (u > T)       sel = true;
            else if (u == T) { sel = (rank < need); rank++; }
            else             sel = false;
            if (sel) atomicOr(&s_bits[i >> 5], 1u << (i & 31));
        }
        __syncthreads();
        for (int i = tid; i < NBW; i += TPB) g_maskbits[i] = s_bits[i];
        __syncthreads();
        if (tid == 0) {
            __threadfence();
            atomicAdd(&g_mask_done, 1u);            // release maskbits
        }
    } else if (b <= 64) {
        // ---- cache bitset for cache (b-1), fully concurrent with select ----
        for (int i = tid; i < NBW; i += TPB) s_mem[i] = 0;
        __syncthreads();
        const int* row = cached + (b - 1) * TOPK_K;
        for (int k = tid; k < TOPK_K; k += TPB) {
            int idx = row[k];
            atomicOr(&s_mem[idx >> 5], 1u << (idx & 31));
        }
        __syncthreads();

        if (tid == 0) poll_ge(&g_mask_done, gen + 1u);
        __syncthreads();

        // ---- deduped intersection ----
        int cnt = 0;
        for (int i = tid; i < NBW; i += TPB)
            cnt += __popc(s_mem[i] & g_maskbits[i]);
        #pragma unroll
        for (int o = 16; o; o >>= 1) cnt += __shfl_down_sync(0xffffffffu, cnt, o);
        __syncthreads();
        if (lane == 0) scanbuf[wid] = cnt;
        __syncthreads();
        if (tid == 0) {
            int s = 0;
            #pragma unroll
            for (int i = 0; i < 32; i++) s += scanbuf[i];
            g_inter[b - 1] = s;
            __threadfence();
            atomicAdd(&g_int_done, 1u);             // one of 64
        }
    }

    // ---- ALL blocks: wait for intersections, decide locally ----
    if (tid == 0) poll_ge(&g_int_done, (gen + 1u) * 64u);
    __syncthreads();

    if (tid == 0) {
        float best = -1.0f; int bi = 0;
        #pragma unroll
        for (int i = 0; i < N_CACHE; i++) {
            float r = (float)g_inter[i] / (float)TOPK_K;
            if (r > best) { best = r; bi = i; }     // first-max = argmax
        }
        s_use  = (best >= 0.9f) ? 1 : 0;
        s_best = bi;
    }
    __syncthreads();

    // ---- build xm in THIS block's smem (parallel across all 128 blocks) ----
    float* s_xf = reinterpret_cast<float*>(s_mem);
    if (!s_use) {
        for (int i = tid; i < N_IN; i += TPB) {
            int sel = (g_maskbits[i >> 5] >> (i & 31)) & 1;
            s_xf[i] = sel ? x[i] : 0.0f;
        }
    } else {
        for (int i = tid; i < N_IN; i += TPB) s_xf[i] = 0.0f;
        __syncthreads();
        const int* brow = cached + s_best * TOPK_K;
        for (int k = tid; k < TOPK_K; k += TPB) {
            int idx = brow[k];
            atomicAdd(&s_xf[idx], x[idx]);          // duplicates = multiplicity
        }
    }
    __syncthreads();

    // ---- GEMV: exact R4 W pattern — 1 row/warp, 4096 x 44KB streams;
    //      x served from smem (conflict-free LDS.128) ----
    const int row = b * 32 + wid;                   // 0..4095
    const float4* __restrict__ w4 = (const float4*)(W + (long long)row * N_IN);
    const float4* __restrict__ x4 = (const float4*)s_xf;

    float a0 = 0.0f, a1 = 0.0f;
    #pragma unroll 4
    for (int it = 0; it < 43; it++) {
        const int j = lane + it * 64;
        float4 w  = __ldcs(w4 + j);
        float4 v  = x4[j];
        a0 += w.x * v.x + w.y * v.y;
        a1 += w.z * v.z + w.w * v.w;
        float4 w2 = __ldcs(w4 + j + 32);
        float4 v2 = x4[j + 32];
        a0 += w2.x * v2.x + w2.y * v2.y;
        a1 += w2.z * v2.z + w2.w * v2.w;
    }
    float acc = a0 + a1;
    #pragma unroll
    for (int o = 16; o; o >>= 1) acc += __shfl_down_sync(0xffffffffu, acc, o);
    if (lane == 0) out[row] = acc + bias[row];
}

// ============================================================================
extern "C" void kernel_launch(void* const* d_in, const int* in_sizes, int n_in,
                              void* d_out, int out_size) {
    const float* x      = (const float*)d_in[0];
    const float* W      = (const float*)d_in[1];
    const float* bias   = (const float*)d_in[2];
    const int*   cached = (const int*)d_in[3];
    float*       out    = (float*)d_out;

    mega_kernel<<<GRID, TPB>>>(x, cached, W, bias, out);
}